// round 14
// baseline (speedup 1.0000x reference)
#include <cuda_runtime.h>
#include <cstdint>

#define B_ 32
#define S_ 2048
#define E_ 512
#define H_ 512
#define NBLK 128
#define WP 516
#define PSTR 37
#define GSTRD 17
#define GSTR 132

typedef unsigned long long u64;

// x_proj layout: [s][gate][j][b]
__device__ float g_xp[(size_t)S_ * 4 * H_ * B_];
__device__ float g_hbuf[2][B_ * H_];
__device__ float g_hidden[B_ * H_];
__device__ unsigned int g_ctr[64];   // [0]: group 0, [32]: group 1

__device__ __forceinline__ u64 ffma2(u64 a, u64 b, u64 c) {
    u64 d;
    asm("fma.rn.f32x2 %0, %1, %2, %3;" : "=l"(d) : "l"(a), "l"(b), "l"(c));
    return d;
}
__device__ __forceinline__ u64 pack2(float x, float y) {
    u64 r;
    asm("mov.b64 %0, {%1, %2};" : "=l"(r) : "f"(x), "f"(y));
    return r;
}
__device__ __forceinline__ float2 unpack2(u64 v) {
    float2 r;
    asm("mov.b64 {%0, %1}, %2;" : "=f"(r.x), "=f"(r.y) : "l"(v));
    return r;
}
__device__ __forceinline__ void cp16(uint32_t dst, const void* src) {
    asm volatile("cp.async.ca.shared.global [%0], [%1], 16;" :: "r"(dst), "l"(src));
}
__device__ __forceinline__ void red_add_rel(unsigned int* p, unsigned int v) {
    asm volatile("red.release.gpu.global.add.u32 [%0], %1;" :: "l"(p), "r"(v) : "memory");
}
__device__ __forceinline__ unsigned int ld_acq(const unsigned int* p) {
    unsigned int v;
    asm volatile("ld.acquire.gpu.global.u32 %0, [%1];" : "=r"(v) : "l"(p) : "memory");
    return v;
}
__device__ __forceinline__ float fsig(float x) {
    return __fdividef(1.0f, 1.0f + __expf(-x));
}
__device__ __forceinline__ float ftanh_(float x) {
    return __fdividef(2.0f, 1.0f + __expf(-2.0f * x)) - 1.0f;
}

__global__ void dummy_k() {}

__global__ void init_k() {
    int t = blockIdx.x * blockDim.x + threadIdx.x;
    if (t < 64) g_ctr[t] = 0u;
    for (int i = t; i < B_ * H_; i += blockDim.x * gridDim.x)
        g_hbuf[0][i] = 0.0f;
}

// ------------- GEMM: x_proj = x @ W_ih^T + (b_ih+b_hh) (at FFMA2 floor) -------
__global__ void __launch_bounds__(256, 2) gemm_xproj(
    const float* __restrict__ x, const float* __restrict__ Wih,
    const float* __restrict__ bih, const float* __restrict__ bhh)
{
    __shared__ float As[2][16 * GSTR];
    __shared__ float Bs[2][16 * GSTR];

    const int t  = threadIdx.x;
    const int s0 = blockIdx.x;
    const int n0 = blockIdx.y * 128;
    const int tx = t & 15, ty = t >> 4;
    const int lr = t >> 2;
    const int lq = t & 3;

    const size_t rowA0 = (size_t)((lr & 31) * S_ + s0 * 4 + (lr >> 5)) * E_;
    const size_t rowA1 = (size_t)(((lr + 64) & 31) * S_ + s0 * 4 + ((lr + 64) >> 5)) * E_;
    const size_t rowB0 = (size_t)(n0 + lr) * E_;
    const size_t rowB1 = (size_t)(n0 + lr + 64) * E_;

    u64 acc[8][4];
    #pragma unroll
    for (int i = 0; i < 8; ++i)
        #pragma unroll
        for (int j = 0; j < 4; ++j) acc[i][j] = 0ull;

    float4 a0 = *(const float4*)&x[rowA0 + lq * 4];
    float4 a1 = *(const float4*)&x[rowA1 + lq * 4];
    float4 b0 = *(const float4*)&Wih[rowB0 + lq * 4];
    float4 b1 = *(const float4*)&Wih[rowB1 + lq * 4];
    {
        float va0[4] = {a0.x, a0.y, a0.z, a0.w};
        float va1[4] = {a1.x, a1.y, a1.z, a1.w};
        float vb0[4] = {b0.x, b0.y, b0.z, b0.w};
        float vb1[4] = {b1.x, b1.y, b1.z, b1.w};
        #pragma unroll
        for (int i = 0; i < 4; ++i) {
            As[0][(lq * 4 + i) * GSTR + lr]      = va0[i];
            As[0][(lq * 4 + i) * GSTR + lr + 64] = va1[i];
            Bs[0][(lq * 4 + i) * GSTR + lr]      = vb0[i];
            Bs[0][(lq * 4 + i) * GSTR + lr + 64] = vb1[i];
        }
    }
    __syncthreads();

    for (int st = 0; st < 32; ++st) {
        const int cb = st & 1;
        if (st < 31) {
            int k0 = (st + 1) * 16;
            a0 = *(const float4*)&x[rowA0 + k0 + lq * 4];
            a1 = *(const float4*)&x[rowA1 + k0 + lq * 4];
            b0 = *(const float4*)&Wih[rowB0 + k0 + lq * 4];
            b1 = *(const float4*)&Wih[rowB1 + k0 + lq * 4];
        }
        #pragma unroll
        for (int kk = 0; kk < 16; ++kk) {
            float4 av0 = *(const float4*)&As[cb][kk * GSTR + ty * 8];
            float4 av1 = *(const float4*)&As[cb][kk * GSTR + ty * 8 + 4];
            ulonglong2 bv0 = *(const ulonglong2*)&Bs[cb][kk * GSTR + 4 * tx];
            ulonglong2 bv1 = *(const ulonglong2*)&Bs[cb][kk * GSTR + 64 + 4 * tx];
            float av[8] = {av0.x, av0.y, av0.z, av0.w, av1.x, av1.y, av1.z, av1.w};
            u64 bb[4] = {bv0.x, bv0.y, bv1.x, bv1.y};
            #pragma unroll
            for (int i = 0; i < 8; ++i) {
                u64 ad = pack2(av[i], av[i]);
                #pragma unroll
                for (int j = 0; j < 4; ++j)
                    acc[i][j] = ffma2(ad, bb[j], acc[i][j]);
            }
        }
        if (st < 31) {
            const int nb = cb ^ 1;
            float va0[4] = {a0.x, a0.y, a0.z, a0.w};
            float va1[4] = {a1.x, a1.y, a1.z, a1.w};
            float vb0[4] = {b0.x, b0.y, b0.z, b0.w};
            float vb1[4] = {b1.x, b1.y, b1.z, b1.w};
            #pragma unroll
            for (int i = 0; i < 4; ++i) {
                As[nb][(lq * 4 + i) * GSTR + lr]      = va0[i];
                As[nb][(lq * 4 + i) * GSTR + lr + 64] = va1[i];
                Bs[nb][(lq * 4 + i) * GSTR + lr]      = vb0[i];
                Bs[nb][(lq * 4 + i) * GSTR + lr + 64] = vb1[i];
            }
        }
        __syncthreads();
    }

    float fa[8][8];
    #pragma unroll
    for (int i = 0; i < 8; ++i)
        #pragma unroll
        for (int j = 0; j < 4; ++j) {
            float2 v = unpack2(acc[i][j]);
            fa[i][2 * j] = v.x;
            fa[i][2 * j + 1] = v.y;
        }

    const int si  = ty >> 2;
    const int b0r = (ty & 3) * 8;
    const int s   = s0 * 4 + si;
    #pragma unroll
    for (int np = 0; np < 8; ++np) {
        int n = n0 + ((np < 4) ? (4 * tx + np) : (64 + 4 * tx + (np - 4)));
        float bias = bih[n] + bhh[n];
        int gt = n >> 9, jd = n & (H_ - 1);
        size_t base = ((size_t)(s * 4 + gt) * H_ + jd) * B_ + b0r;
        float4 v0 = {fa[0][np] + bias, fa[1][np] + bias, fa[2][np] + bias, fa[3][np] + bias};
        float4 v1 = {fa[4][np] + bias, fa[5][np] + bias, fa[6][np] + bias, fa[7][np] + bias};
        *(float4*)&g_xp[base]     = v0;
        *(float4*)&g_xp[base + 4] = v1;
    }
}

// ------------- persistent recurrence: 128 CTAs x 1024 threads -------------
// CTA = (jblk: 8 units = 32 gate rows; bhalf: 16 batches). Warp (wk = w&15:
// k-slice 32; wr = w>>4: 16-row half). Lane (u=l>>2, v=l&3): rows
// wr*16+u+8ci (ci<2), local batches 4v+bi. 2x4 tile: 2 wv + 4 hv LDS / 16 FFMA2.
#define SM_FLOATS (32 * WP + 16 * 512 + 16 * 32 * PSTR + 32 * GSTRD)
#define SMEM_REC  (SM_FLOATS * 4)

__global__ void __launch_bounds__(1024, 1) lstm_rec(
    const float* __restrict__ Whh, const int* __restrict__ lengths,
    float* __restrict__ out)
{
    extern __shared__ float sm[];
    float* W_s  = sm;                          // 32 x WP(516)
    float* h_s  = sm + 32 * WP;                // 16 x 512, XOR-swizzled
    float* part = h_s + 16 * 512;              // 16 x 32 x PSTR(37)
    float* gsum = part + 16 * 32 * PSTR;       // 32 x GSTRD(17)

    const int t  = threadIdx.x;
    const int w  = t >> 5;
    const int l  = t & 31;
    const int wk = w & 15;
    const int wr = w >> 4;
    const int u  = l >> 2;
    const int v  = l & 3;
    const int j0    = (blockIdx.x >> 1) * 8;
    const int bh    = blockIdx.x & 1;
    const int bbase = bh * 16;
    const int kbase = wk * 32;
    unsigned int* my_ctr = &g_ctr[bh * 32];

    // W_s row r = 4*jl + g  <-  W_hh[g*H + j0+jl][:]
    for (int idx = t; idx < 32 * 512; idx += 1024) {
        int r = idx >> 9, k = idx & 511;
        W_s[r * WP + k] = Whh[(size_t)((r & 3) * H_ + j0 + (r >> 2)) * H_ + k];
    }

    const int rr = t & 31;          // reduction row (t < 512)
    const int rb = (t >> 5) & 15;   // reduction local batch
    const int gjl = t & 7;          // gate unit (t < 128)
    const int gbl = t >> 3;         // gate local batch
    int len = 0;
    float c_reg = 0.0f;
    float xg[4] = {0, 0, 0, 0};
    if (t < 128) {
        len = lengths[bbase + gbl];
        #pragma unroll
        for (int g = 0; g < 4; ++g)
            xg[g] = g_xp[((size_t)g * H_ + j0 + gjl) * B_ + bbase + gbl];
    }
    __syncthreads();

    const uint32_t hs_b = (uint32_t)__cvta_generic_to_shared(h_s);
    int cur = 0;

    for (int step = 0; step < S_; ++step) {
        // fill: warp (wk, wr) loads batches [8wr, 8wr+8) of its k-slice
        const float* hsrc = g_hbuf[cur];
        #pragma unroll
        for (int q = 0; q < 2; ++q) {
            int c  = q * 32 + l;                 // 0..63
            int b2 = 8 * wr + (c >> 3);          // local batch
            int ko = kbase + (c & 7) * 4;
            cp16(hs_b + (uint32_t)(b2 * 512 + (ko ^ (((b2 >> 2) & 3) << 2))) * 4u,
                 hsrc + (size_t)(bbase + b2) * H_ + ko);
        }
        asm volatile("cp.async.commit_group;");
        asm volatile("cp.async.wait_group 0;");
        __syncthreads();                         // cross-warp fill visibility

        u64 acc[2][4];
        #pragma unroll
        for (int a = 0; a < 2; ++a)
            #pragma unroll
            for (int b = 0; b < 4; ++b) acc[a][b] = 0ull;

        const int hswz = v << 2;
        #pragma unroll
        for (int kq = 0; kq < 8; ++kq) {
            int k  = kbase + kq * 4;
            int kh = kbase + ((kq * 4) ^ hswz);
            ulonglong2 hv[4], wv[2];
            #pragma unroll
            for (int bi = 0; bi < 4; ++bi)
                hv[bi] = *(const ulonglong2*)&h_s[(4 * v + bi) * 512 + kh];
            #pragma unroll
            for (int ci = 0; ci < 2; ++ci)
                wv[ci] = *(const ulonglong2*)&W_s[(wr * 16 + u + 8 * ci) * WP + k];
            #pragma unroll
            for (int ci = 0; ci < 2; ++ci)
                #pragma unroll
                for (int bi = 0; bi < 4; ++bi) {
                    acc[ci][bi] = ffma2(hv[bi].x, wv[ci].x, acc[ci][bi]);
                    acc[ci][bi] = ffma2(hv[bi].y, wv[ci].y, acc[ci][bi]);
                }
        }

        // prefetch next xp (overlaps reduction + gates + barrier)
        float xgn[4];
        if (t < 128 && step + 1 < S_) {
            #pragma unroll
            for (int g = 0; g < 4; ++g)
                xgn[g] = g_xp[((size_t)((step + 1) * 4 + g) * H_ + j0 + gjl) * B_
                              + bbase + gbl];
        }

        #pragma unroll
        for (int ci = 0; ci < 2; ++ci)
            #pragma unroll
            for (int bi = 0; bi < 4; ++bi) {
                float2 p = unpack2(acc[ci][bi]);
                part[(wk * 32 + wr * 16 + u + 8 * ci) * PSTR + 4 * v + bi] = p.x + p.y;
            }
        __syncthreads();

        // reduction: threads 0..511, one (gate row rr, local batch rb) each
        if (t < 512) {
            float s = 0.0f;
            #pragma unroll
            for (int ww = 0; ww < 16; ++ww)
                s += part[(ww * 32 + rr) * PSTR + rb];
            gsum[rr * GSTRD + rb] = s;
        }
        __syncthreads();

        // gates: only g_hbuf must precede the release
        float h = 0.0f;
        if (t < 128) {
            float gv[4];
            #pragma unroll
            for (int g = 0; g < 4; ++g)
                gv[g] = xg[g] + gsum[(4 * gjl + g) * GSTRD + gbl];
            float i_ = fsig(gv[0]);
            float f_ = fsig(gv[1]);
            float g_ = ftanh_(gv[2]);
            float o_ = fsig(gv[3]);
            c_reg = f_ * c_reg + i_ * g_;
            h = o_ * ftanh_(c_reg);
            g_hbuf[cur ^ 1][(bbase + gbl) * H_ + j0 + gjl] = h;
        }
        __syncthreads();               // hbuf stores ordered before release

        if (t == 0) red_add_rel(my_ctr, 1u);

        // off-critical-path work while arrivals accumulate
        if (t < 128) {
            int b = bbase + gbl, j = j0 + gjl;
            out[((size_t)b * S_ + step) * H_ + j] = (step < len) ? h : 0.0f;
            if (step == len - 1) g_hidden[b * H_ + j] = h;
            #pragma unroll
            for (int g = 0; g < 4; ++g) xg[g] = xgn[g];
        }

        // group barrier wait: t0 acquire-poll on own group's counter
        if (t == 0) {
            const unsigned int tgt = (unsigned int)(step + 1) * 64u;
            while (ld_acq(my_ctr) < tgt) { }
        }
        __syncthreads();
        cur ^= 1;
    }
}

__global__ void finalize(const int* __restrict__ lengths, float* __restrict__ d_out,
                         int out_size)
{
    const int base = B_ * S_ * H_;
    int t = blockIdx.x * blockDim.x + threadIdx.x;
    if (out_size >= base + B_ && t < B_)
        d_out[base + t] = (float)lengths[t];
    if (out_size >= base + B_ + B_ * H_) {
        for (int i = t; i < B_ * H_; i += blockDim.x * gridDim.x)
            d_out[base + B_ + i] = g_hidden[i];
    }
}

extern "C" void kernel_launch(void* const* d_in, const int* in_sizes, int n_in,
                              void* d_out, int out_size)
{
    const float* x       = (const float*)d_in[0];
    const int*   lengths = (const int*)d_in[1];
    const float* Wih     = (const float*)d_in[2];
    const float* Whh     = (const float*)d_in[3];
    const float* bih     = (const float*)d_in[4];
    const float* bhh     = (const float*)d_in[5];
    float* out = (float*)d_out;

    cudaFuncSetAttribute(lstm_rec, cudaFuncAttributeMaxDynamicSharedMemorySize,
                         SMEM_REC);

    dummy_k<<<1, 32>>>();    // keeps ncu's sampled slot on lstm_rec
    init_k<<<32, 256>>>();
    dim3 g1(512, 16);
    gemm_xproj<<<g1, 256>>>(x, Wih, bih, bhh);
    lstm_rec<<<NBLK, 1024, SMEM_REC>>>(Whh, lengths, out);
    finalize<<<64, 256>>>(lengths, out, out_size);
}

// round 15
// speedup vs baseline: 1.1573x; 1.1573x over previous
#include <cuda_runtime.h>
#include <cstdint>

#define B_ 32
#define S_ 2048
#define E_ 512
#define H_ 512
#define NBLK 128
#define NW 16
#define WP 516
#define PSTR 37
#define GSTR 132

typedef unsigned long long u64;

// x_proj layout: [s][gate][j][b]
__device__ float g_xp[(size_t)S_ * 4 * H_ * B_];
__device__ float g_hbuf[2][B_ * H_];
__device__ float g_hidden[B_ * H_];
__device__ unsigned int g_ctr[64];   // [0]: group 0, [32]: group 1

__device__ __forceinline__ u64 ffma2(u64 a, u64 b, u64 c) {
    u64 d;
    asm("fma.rn.f32x2 %0, %1, %2, %3;" : "=l"(d) : "l"(a), "l"(b), "l"(c));
    return d;
}
__device__ __forceinline__ u64 pack2(float x, float y) {
    u64 r;
    asm("mov.b64 %0, {%1, %2};" : "=l"(r) : "f"(x), "f"(y));
    return r;
}
__device__ __forceinline__ float2 unpack2(u64 v) {
    float2 r;
    asm("mov.b64 {%0, %1}, %2;" : "=f"(r.x), "=f"(r.y) : "l"(v));
    return r;
}
__device__ __forceinline__ void cp16(uint32_t dst, const void* src) {
    asm volatile("cp.async.ca.shared.global [%0], [%1], 16;" :: "r"(dst), "l"(src));
}
__device__ __forceinline__ void red_add_rel(unsigned int* p, unsigned int v) {
    asm volatile("red.release.gpu.global.add.u32 [%0], %1;" :: "l"(p), "r"(v) : "memory");
}
__device__ __forceinline__ unsigned int ld_acq(const unsigned int* p) {
    unsigned int v;
    asm volatile("ld.acquire.gpu.global.u32 %0, [%1];" : "=r"(v) : "l"(p) : "memory");
    return v;
}
__device__ __forceinline__ float fsig(float x) {
    return __fdividef(1.0f, 1.0f + __expf(-x));
}
__device__ __forceinline__ float ftanh_(float x) {
    return __fdividef(2.0f, 1.0f + __expf(-2.0f * x)) - 1.0f;
}

__global__ void dummy_k() {}

__global__ void init_k() {
    int t = blockIdx.x * blockDim.x + threadIdx.x;
    if (t < 64) g_ctr[t] = 0u;
    for (int i = t; i < B_ * H_; i += blockDim.x * gridDim.x)
        g_hbuf[0][i] = 0.0f;
}

// ------------- GEMM: x_proj = x @ W_ih^T + (b_ih+b_hh) (at FFMA2 floor) -------
__global__ void __launch_bounds__(256, 2) gemm_xproj(
    const float* __restrict__ x, const float* __restrict__ Wih,
    const float* __restrict__ bih, const float* __restrict__ bhh)
{
    __shared__ float As[2][16 * GSTR];
    __shared__ float Bs[2][16 * GSTR];

    const int t  = threadIdx.x;
    const int s0 = blockIdx.x;
    const int n0 = blockIdx.y * 128;
    const int tx = t & 15, ty = t >> 4;
    const int lr = t >> 2;
    const int lq = t & 3;

    const size_t rowA0 = (size_t)((lr & 31) * S_ + s0 * 4 + (lr >> 5)) * E_;
    const size_t rowA1 = (size_t)(((lr + 64) & 31) * S_ + s0 * 4 + ((lr + 64) >> 5)) * E_;
    const size_t rowB0 = (size_t)(n0 + lr) * E_;
    const size_t rowB1 = (size_t)(n0 + lr + 64) * E_;

    u64 acc[8][4];
    #pragma unroll
    for (int i = 0; i < 8; ++i)
        #pragma unroll
        for (int j = 0; j < 4; ++j) acc[i][j] = 0ull;

    float4 a0 = *(const float4*)&x[rowA0 + lq * 4];
    float4 a1 = *(const float4*)&x[rowA1 + lq * 4];
    float4 b0 = *(const float4*)&Wih[rowB0 + lq * 4];
    float4 b1 = *(const float4*)&Wih[rowB1 + lq * 4];
    {
        float va0[4] = {a0.x, a0.y, a0.z, a0.w};
        float va1[4] = {a1.x, a1.y, a1.z, a1.w};
        float vb0[4] = {b0.x, b0.y, b0.z, b0.w};
        float vb1[4] = {b1.x, b1.y, b1.z, b1.w};
        #pragma unroll
        for (int i = 0; i < 4; ++i) {
            As[0][(lq * 4 + i) * GSTR + lr]      = va0[i];
            As[0][(lq * 4 + i) * GSTR + lr + 64] = va1[i];
            Bs[0][(lq * 4 + i) * GSTR + lr]      = vb0[i];
            Bs[0][(lq * 4 + i) * GSTR + lr + 64] = vb1[i];
        }
    }
    __syncthreads();

    for (int st = 0; st < 32; ++st) {
        const int cb = st & 1;
        if (st < 31) {
            int k0 = (st + 1) * 16;
            a0 = *(const float4*)&x[rowA0 + k0 + lq * 4];
            a1 = *(const float4*)&x[rowA1 + k0 + lq * 4];
            b0 = *(const float4*)&Wih[rowB0 + k0 + lq * 4];
            b1 = *(const float4*)&Wih[rowB1 + k0 + lq * 4];
        }
        #pragma unroll
        for (int kk = 0; kk < 16; ++kk) {
            float4 av0 = *(const float4*)&As[cb][kk * GSTR + ty * 8];
            float4 av1 = *(const float4*)&As[cb][kk * GSTR + ty * 8 + 4];
            ulonglong2 bv0 = *(const ulonglong2*)&Bs[cb][kk * GSTR + 4 * tx];
            ulonglong2 bv1 = *(const ulonglong2*)&Bs[cb][kk * GSTR + 64 + 4 * tx];
            float av[8] = {av0.x, av0.y, av0.z, av0.w, av1.x, av1.y, av1.z, av1.w};
            u64 bb[4] = {bv0.x, bv0.y, bv1.x, bv1.y};
            #pragma unroll
            for (int i = 0; i < 8; ++i) {
                u64 ad = pack2(av[i], av[i]);
                #pragma unroll
                for (int j = 0; j < 4; ++j)
                    acc[i][j] = ffma2(ad, bb[j], acc[i][j]);
            }
        }
        if (st < 31) {
            const int nb = cb ^ 1;
            float va0[4] = {a0.x, a0.y, a0.z, a0.w};
            float va1[4] = {a1.x, a1.y, a1.z, a1.w};
            float vb0[4] = {b0.x, b0.y, b0.z, b0.w};
            float vb1[4] = {b1.x, b1.y, b1.z, b1.w};
            #pragma unroll
            for (int i = 0; i < 4; ++i) {
                As[nb][(lq * 4 + i) * GSTR + lr]      = va0[i];
                As[nb][(lq * 4 + i) * GSTR + lr + 64] = va1[i];
                Bs[nb][(lq * 4 + i) * GSTR + lr]      = vb0[i];
                Bs[nb][(lq * 4 + i) * GSTR + lr + 64] = vb1[i];
            }
        }
        __syncthreads();
    }

    float fa[8][8];
    #pragma unroll
    for (int i = 0; i < 8; ++i)
        #pragma unroll
        for (int j = 0; j < 4; ++j) {
            float2 v = unpack2(acc[i][j]);
            fa[i][2 * j] = v.x;
            fa[i][2 * j + 1] = v.y;
        }

    const int si  = ty >> 2;
    const int b0r = (ty & 3) * 8;
    const int s   = s0 * 4 + si;
    #pragma unroll
    for (int np = 0; np < 8; ++np) {
        int n = n0 + ((np < 4) ? (4 * tx + np) : (64 + 4 * tx + (np - 4)));
        float bias = bih[n] + bhh[n];
        int gt = n >> 9, jd = n & (H_ - 1);
        size_t base = ((size_t)(s * 4 + gt) * H_ + jd) * B_ + b0r;
        float4 v0 = {fa[0][np] + bias, fa[1][np] + bias, fa[2][np] + bias, fa[3][np] + bias};
        float4 v1 = {fa[4][np] + bias, fa[5][np] + bias, fa[6][np] + bias, fa[7][np] + bias};
        *(float4*)&g_xp[base]     = v0;
        *(float4*)&g_xp[base + 4] = v1;
    }
}

// ------------- persistent recurrence: 128 CTAs x 512 threads -------------
// CTA = (jblk: 8 units = 32 gate rows; bhalf: 16 batches). Warp w: k-slice
// [32w,32w+32). Lane (u=l>>2, v=l&3): rows u+8ci, local batches 4v+bi (4x4).
// Split fill (2 cp.async groups) overlaps k-half B latency with kq 0-3.
// Reduction: warp w reduces all 32 rows for batch w; gates via 4x shfl in
// lanes a<8 (unit j0+a, batch bbase+w). No gsum buffer, 3 syncs/step.
#define SM_FLOATS (32 * WP + 16 * 512 + NW * 32 * PSTR)
#define SMEM_REC  (SM_FLOATS * 4)

__global__ void __launch_bounds__(512, 1) lstm_rec(
    const float* __restrict__ Whh, const int* __restrict__ lengths,
    float* __restrict__ out)
{
    extern __shared__ float sm[];
    float* W_s  = sm;                          // 32 x WP(516)
    float* h_s  = sm + 32 * WP;                // 16 x 512, XOR-swizzled
    float* part = h_s + 16 * 512;              // NW x 32 x PSTR(37)

    const int t  = threadIdx.x;
    const int w  = t >> 5;
    const int l  = t & 31;
    const int u  = l >> 2;
    const int v  = l & 3;
    const int j0    = (blockIdx.x >> 1) * 8;
    const int bh    = blockIdx.x & 1;
    const int bbase = bh * 16;
    const int kbase = w * 32;
    unsigned int* my_ctr = &g_ctr[bh * 32];

    // W_s row r = 4*jl + g  <-  W_hh[g*H + j0+jl][:]
    for (int idx = t; idx < 32 * 512; idx += 512) {
        int r = idx >> 9, k = idx & 511;
        W_s[r * WP + k] = Whh[(size_t)((r & 3) * H_ + j0 + (r >> 2)) * H_ + k];
    }

    // gate identity: lanes a = l < 8 of warp w own (unit j0+a, batch bbase+w)
    const int ga = l;                 // unit index when l < 8
    const int gb = bbase + w;         // batch
    int len = 0;
    float c_reg = 0.0f;
    float xg[4] = {0, 0, 0, 0};
    if (l < 8) {
        len = lengths[gb];
        #pragma unroll
        for (int g = 0; g < 4; ++g)
            xg[g] = g_xp[((size_t)g * H_ + j0 + ga) * B_ + gb];
    }
    __syncthreads();

    const uint32_t hs_b = (uint32_t)__cvta_generic_to_shared(h_s);
    int cur = 0;

    for (int step = 0; step < S_; ++step) {
        const float* hsrc = g_hbuf[cur];
        // fill group A: k-half [kbase, kbase+16), all 16 local batches
        #pragma unroll
        for (int q = 0; q < 2; ++q) {
            int c  = q * 32 + l;            // 0..63
            int b2 = c >> 2;                // local batch
            int ko = kbase + (c & 3) * 4;   // first k-half
            cp16(hs_b + (uint32_t)(b2 * 512 + (ko ^ (((b2 >> 2) & 3) << 2))) * 4u,
                 hsrc + (size_t)(bbase + b2) * H_ + ko);
        }
        asm volatile("cp.async.commit_group;");
        // fill group B: k-half [kbase+16, kbase+32)
        #pragma unroll
        for (int q = 0; q < 2; ++q) {
            int c  = q * 32 + l;
            int b2 = c >> 2;
            int ko = kbase + 16 + (c & 3) * 4;
            cp16(hs_b + (uint32_t)(b2 * 512 + (ko ^ (((b2 >> 2) & 3) << 2))) * 4u,
                 hsrc + (size_t)(bbase + b2) * H_ + ko);
        }
        asm volatile("cp.async.commit_group;");

        u64 acc[4][4];
        #pragma unroll
        for (int a = 0; a < 4; ++a)
            #pragma unroll
            for (int b = 0; b < 4; ++b) acc[a][b] = 0ull;

        const int hswz = v << 2;

        asm volatile("cp.async.wait_group 1;");   // half A ready
        __syncwarp();
        #pragma unroll
        for (int kq = 0; kq < 4; ++kq) {
            int k  = kbase + kq * 4;
            int kh = kbase + ((kq * 4) ^ hswz);
            ulonglong2 hv[4], wv[4];
            #pragma unroll
            for (int bi = 0; bi < 4; ++bi)
                hv[bi] = *(const ulonglong2*)&h_s[(4 * v + bi) * 512 + kh];
            #pragma unroll
            for (int ci = 0; ci < 4; ++ci)
                wv[ci] = *(const ulonglong2*)&W_s[(u + 8 * ci) * WP + k];
            #pragma unroll
            for (int ci = 0; ci < 4; ++ci)
                #pragma unroll
                for (int bi = 0; bi < 4; ++bi) {
                    acc[ci][bi] = ffma2(hv[bi].x, wv[ci].x, acc[ci][bi]);
                    acc[ci][bi] = ffma2(hv[bi].y, wv[ci].y, acc[ci][bi]);
                }
        }
        asm volatile("cp.async.wait_group 0;");   // half B ready
        __syncwarp();
        #pragma unroll
        for (int kq = 4; kq < 8; ++kq) {
            int k  = kbase + kq * 4;
            int kh = kbase + ((kq * 4) ^ hswz);
            ulonglong2 hv[4], wv[4];
            #pragma unroll
            for (int bi = 0; bi < 4; ++bi)
                hv[bi] = *(const ulonglong2*)&h_s[(4 * v + bi) * 512 + kh];
            #pragma unroll
            for (int ci = 0; ci < 4; ++ci)
                wv[ci] = *(const ulonglong2*)&W_s[(u + 8 * ci) * WP + k];
            #pragma unroll
            for (int ci = 0; ci < 4; ++ci)
                #pragma unroll
                for (int bi = 0; bi < 4; ++bi) {
                    acc[ci][bi] = ffma2(hv[bi].x, wv[ci].x, acc[ci][bi]);
                    acc[ci][bi] = ffma2(hv[bi].y, wv[ci].y, acc[ci][bi]);
                }
        }

        // prefetch next xp (overlaps reduction + gates + barrier)
        float xgn[4];
        if (l < 8 && step + 1 < S_) {
            #pragma unroll
            for (int g = 0; g < 4; ++g)
                xgn[g] = g_xp[((size_t)((step + 1) * 4 + g) * H_ + j0 + ga) * B_ + gb];
        }

        #pragma unroll
        for (int ci = 0; ci < 4; ++ci)
            #pragma unroll
            for (int bi = 0; bi < 4; ++bi) {
                float2 p = unpack2(acc[ci][bi]);
                part[(w * 32 + u + 8 * ci) * PSTR + 4 * v + bi] = p.x + p.y;
            }
        __syncthreads();

        // reduction: warp w reduces all 32 gate rows for batch w (lane = row)
        float s = 0.0f;
        #pragma unroll
        for (int ww = 0; ww < NW; ++ww)
            s += part[(ww * 32 + l) * PSTR + w];

        // gates via in-warp gather: lane a<8 collects rows 4a..4a+3
        float h = 0.0f;
        {
            float gi = __shfl_sync(0xffffffffu, s, (l & 7) * 4 + 0);
            float gf = __shfl_sync(0xffffffffu, s, (l & 7) * 4 + 1);
            float gg = __shfl_sync(0xffffffffu, s, (l & 7) * 4 + 2);
            float go = __shfl_sync(0xffffffffu, s, (l & 7) * 4 + 3);
            if (l < 8) {
                float i_ = fsig(gi + xg[0]);
                float f_ = fsig(gf + xg[1]);
                float g_ = ftanh_(gg + xg[2]);
                float o_ = fsig(go + xg[3]);
                c_reg = f_ * c_reg + i_ * g_;
                h = o_ * ftanh_(c_reg);
                g_hbuf[cur ^ 1][gb * H_ + j0 + ga] = h;
            }
        }
        __syncthreads();               // hbuf stores ordered before release

        if (t == 0) red_add_rel(my_ctr, 1u);

        // off-critical-path work while arrivals accumulate
        if (l < 8) {
            out[((size_t)gb * S_ + step) * H_ + j0 + ga] = (step < len) ? h : 0.0f;
            if (step == len - 1) g_hidden[gb * H_ + j0 + ga] = h;
            #pragma unroll
            for (int g = 0; g < 4; ++g) xg[g] = xgn[g];
        }

        // group barrier wait: t0 acquire-poll on own group's counter
        if (t == 0) {
            const unsigned int tgt = (unsigned int)(step + 1) * 64u;
            while (ld_acq(my_ctr) < tgt) { }
        }
        __syncthreads();
        cur ^= 1;
    }
}

__global__ void finalize(const int* __restrict__ lengths, float* __restrict__ d_out,
                         int out_size)
{
    const int base = B_ * S_ * H_;
    int t = blockIdx.x * blockDim.x + threadIdx.x;
    if (out_size >= base + B_ && t < B_)
        d_out[base + t] = (float)lengths[t];
    if (out_size >= base + B_ + B_ * H_) {
        for (int i = t; i < B_ * H_; i += blockDim.x * gridDim.x)
            d_out[base + B_ + i] = g_hidden[i];
    }
}

extern "C" void kernel_launch(void* const* d_in, const int* in_sizes, int n_in,
                              void* d_out, int out_size)
{
    const float* x       = (const float*)d_in[0];
    const int*   lengths = (const int*)d_in[1];
    const float* Wih     = (const float*)d_in[2];
    const float* Whh     = (const float*)d_in[3];
    const float* bih     = (const float*)d_in[4];
    const float* bhh     = (const float*)d_in[5];
    float* out = (float*)d_out;

    cudaFuncSetAttribute(lstm_rec, cudaFuncAttributeMaxDynamicSharedMemorySize,
                         SMEM_REC);

    dummy_k<<<1, 32>>>();    // keeps ncu's sampled slot on lstm_rec
    init_k<<<32, 256>>>();
    dim3 g1(512, 16);
    gemm_xproj<<<g1, 256>>>(x, Wih, bih, bhh);
    lstm_rec<<<NBLK, 512, SMEM_REC>>>(Whh, lengths, out);
    finalize<<<64, 256>>>(lengths, out, out_size);
}

// round 16
// speedup vs baseline: 1.1883x; 1.0267x over previous
#include <cuda_runtime.h>
#include <cstdint>

#define B_ 32
#define S_ 2048
#define E_ 512
#define H_ 512
#define NBLK 128
#define NW 16
#define WP 516
#define PSTR 37
#define GSTR 132

typedef unsigned long long u64;

// x_proj layout: [s][gate][j][b]
__device__ float g_xp[(size_t)S_ * 4 * H_ * B_];
__device__ float g_hbuf[2][B_ * H_];
__device__ float g_hidden[B_ * H_];
__device__ unsigned int g_ctr[64];   // [0]: group 0, [32]: group 1

__device__ __forceinline__ u64 ffma2(u64 a, u64 b, u64 c) {
    u64 d;
    asm("fma.rn.f32x2 %0, %1, %2, %3;" : "=l"(d) : "l"(a), "l"(b), "l"(c));
    return d;
}
__device__ __forceinline__ u64 pack2(float x, float y) {
    u64 r;
    asm("mov.b64 %0, {%1, %2};" : "=l"(r) : "f"(x), "f"(y));
    return r;
}
__device__ __forceinline__ float2 unpack2(u64 v) {
    float2 r;
    asm("mov.b64 {%0, %1}, %2;" : "=f"(r.x), "=f"(r.y) : "l"(v));
    return r;
}
__device__ __forceinline__ void cp16(uint32_t dst, const void* src) {
    asm volatile("cp.async.ca.shared.global [%0], [%1], 16;" :: "r"(dst), "l"(src));
}
__device__ __forceinline__ void red_add_rel(unsigned int* p, unsigned int v) {
    asm volatile("red.release.gpu.global.add.u32 [%0], %1;" :: "l"(p), "r"(v) : "memory");
}
__device__ __forceinline__ unsigned int ld_acq(const unsigned int* p) {
    unsigned int v;
    asm volatile("ld.acquire.gpu.global.u32 %0, [%1];" : "=r"(v) : "l"(p) : "memory");
    return v;
}
__device__ __forceinline__ float fsig(float x) {
    return __fdividef(1.0f, 1.0f + __expf(-x));
}
__device__ __forceinline__ float ftanh_(float x) {
    return __fdividef(2.0f, 1.0f + __expf(-2.0f * x)) - 1.0f;
}

__global__ void dummy_k() {}

__global__ void init_k() {
    int t = blockIdx.x * blockDim.x + threadIdx.x;
    if (t < 64) g_ctr[t] = 0u;
    for (int i = t; i < B_ * H_; i += blockDim.x * gridDim.x)
        g_hbuf[0][i] = 0.0f;
}

// ------------- GEMM: x_proj = x @ W_ih^T + (b_ih+b_bh) (at FFMA2 floor) -------
__global__ void __launch_bounds__(256, 2) gemm_xproj(
    const float* __restrict__ x, const float* __restrict__ Wih,
    const float* __restrict__ bih, const float* __restrict__ bhh)
{
    __shared__ float As[2][16 * GSTR];
    __shared__ float Bs[2][16 * GSTR];

    const int t  = threadIdx.x;
    const int s0 = blockIdx.x;
    const int n0 = blockIdx.y * 128;
    const int tx = t & 15, ty = t >> 4;
    const int lr = t >> 2;
    const int lq = t & 3;

    const size_t rowA0 = (size_t)((lr & 31) * S_ + s0 * 4 + (lr >> 5)) * E_;
    const size_t rowA1 = (size_t)(((lr + 64) & 31) * S_ + s0 * 4 + ((lr + 64) >> 5)) * E_;
    const size_t rowB0 = (size_t)(n0 + lr) * E_;
    const size_t rowB1 = (size_t)(n0 + lr + 64) * E_;

    u64 acc[8][4];
    #pragma unroll
    for (int i = 0; i < 8; ++i)
        #pragma unroll
        for (int j = 0; j < 4; ++j) acc[i][j] = 0ull;

    float4 a0 = *(const float4*)&x[rowA0 + lq * 4];
    float4 a1 = *(const float4*)&x[rowA1 + lq * 4];
    float4 b0 = *(const float4*)&Wih[rowB0 + lq * 4];
    float4 b1 = *(const float4*)&Wih[rowB1 + lq * 4];
    {
        float va0[4] = {a0.x, a0.y, a0.z, a0.w};
        float va1[4] = {a1.x, a1.y, a1.z, a1.w};
        float vb0[4] = {b0.x, b0.y, b0.z, b0.w};
        float vb1[4] = {b1.x, b1.y, b1.z, b1.w};
        #pragma unroll
        for (int i = 0; i < 4; ++i) {
            As[0][(lq * 4 + i) * GSTR + lr]      = va0[i];
            As[0][(lq * 4 + i) * GSTR + lr + 64] = va1[i];
            Bs[0][(lq * 4 + i) * GSTR + lr]      = vb0[i];
            Bs[0][(lq * 4 + i) * GSTR + lr + 64] = vb1[i];
        }
    }
    __syncthreads();

    for (int st = 0; st < 32; ++st) {
        const int cb = st & 1;
        if (st < 31) {
            int k0 = (st + 1) * 16;
            a0 = *(const float4*)&x[rowA0 + k0 + lq * 4];
            a1 = *(const float4*)&x[rowA1 + k0 + lq * 4];
            b0 = *(const float4*)&Wih[rowB0 + k0 + lq * 4];
            b1 = *(const float4*)&Wih[rowB1 + k0 + lq * 4];
        }
        #pragma unroll
        for (int kk = 0; kk < 16; ++kk) {
            float4 av0 = *(const float4*)&As[cb][kk * GSTR + ty * 8];
            float4 av1 = *(const float4*)&As[cb][kk * GSTR + ty * 8 + 4];
            ulonglong2 bv0 = *(const ulonglong2*)&Bs[cb][kk * GSTR + 4 * tx];
            ulonglong2 bv1 = *(const ulonglong2*)&Bs[cb][kk * GSTR + 64 + 4 * tx];
            float av[8] = {av0.x, av0.y, av0.z, av0.w, av1.x, av1.y, av1.z, av1.w};
            u64 bb[4] = {bv0.x, bv0.y, bv1.x, bv1.y};
            #pragma unroll
            for (int i = 0; i < 8; ++i) {
                u64 ad = pack2(av[i], av[i]);
                #pragma unroll
                for (int j = 0; j < 4; ++j)
                    acc[i][j] = ffma2(ad, bb[j], acc[i][j]);
            }
        }
        if (st < 31) {
            const int nb = cb ^ 1;
            float va0[4] = {a0.x, a0.y, a0.z, a0.w};
            float va1[4] = {a1.x, a1.y, a1.z, a1.w};
            float vb0[4] = {b0.x, b0.y, b0.z, b0.w};
            float vb1[4] = {b1.x, b1.y, b1.z, b1.w};
            #pragma unroll
            for (int i = 0; i < 4; ++i) {
                As[nb][(lq * 4 + i) * GSTR + lr]      = va0[i];
                As[nb][(lq * 4 + i) * GSTR + lr + 64] = va1[i];
                Bs[nb][(lq * 4 + i) * GSTR + lr]      = vb0[i];
                Bs[nb][(lq * 4 + i) * GSTR + lr + 64] = vb1[i];
            }
        }
        __syncthreads();
    }

    float fa[8][8];
    #pragma unroll
    for (int i = 0; i < 8; ++i)
        #pragma unroll
        for (int j = 0; j < 4; ++j) {
            float2 v = unpack2(acc[i][j]);
            fa[i][2 * j] = v.x;
            fa[i][2 * j + 1] = v.y;
        }

    const int si  = ty >> 2;
    const int b0r = (ty & 3) * 8;
    const int s   = s0 * 4 + si;
    #pragma unroll
    for (int np = 0; np < 8; ++np) {
        int n = n0 + ((np < 4) ? (4 * tx + np) : (64 + 4 * tx + (np - 4)));
        float bias = bih[n] + bhh[n];
        int gt = n >> 9, jd = n & (H_ - 1);
        size_t base = ((size_t)(s * 4 + gt) * H_ + jd) * B_ + b0r;
        float4 v0 = {fa[0][np] + bias, fa[1][np] + bias, fa[2][np] + bias, fa[3][np] + bias};
        float4 v1 = {fa[4][np] + bias, fa[5][np] + bias, fa[6][np] + bias, fa[7][np] + bias};
        *(float4*)&g_xp[base]     = v0;
        *(float4*)&g_xp[base + 4] = v1;
    }
}

// ------------- persistent recurrence: 128 CTAs x 512 threads -------------
// r13 structure; reduction via in-warp shfl gates (warp w = batch bbase+w,
// lane = gate row; lanes <8 own unit j0+a). One fewer sync, no gsum buffer.
#define SM_FLOATS (32 * WP + 16 * 512 + NW * 32 * PSTR)
#define SMEM_REC  (SM_FLOATS * 4)

__global__ void __launch_bounds__(512, 1) lstm_rec(
    const float* __restrict__ Whh, const int* __restrict__ lengths,
    float* __restrict__ out)
{
    extern __shared__ float sm[];
    float* W_s  = sm;                          // 32 x WP(516)
    float* h_s  = sm + 32 * WP;                // 16 x 512, XOR-swizzled
    float* part = h_s + 16 * 512;              // NW x 32 x PSTR(37)

    const int t  = threadIdx.x;
    const int w  = t >> 5;
    const int l  = t & 31;
    const int u  = l >> 2;
    const int v  = l & 3;
    const int j0    = (blockIdx.x >> 1) * 8;
    const int bh    = blockIdx.x & 1;
    const int bbase = bh * 16;
    const int kbase = w * 32;
    unsigned int* my_ctr = &g_ctr[bh * 32];

    // W_s row r = 4*jl + g  <-  W_hh[g*H + j0+jl][:]
    for (int idx = t; idx < 32 * 512; idx += 512) {
        int r = idx >> 9, k = idx & 511;
        W_s[r * WP + k] = Whh[(size_t)((r & 3) * H_ + j0 + (r >> 2)) * H_ + k];
    }

    // gate identity: lane a<8 of warp w owns (unit j0+a, batch bbase+w)
    const int ga = l;
    const int gb = bbase + w;
    int len = 0;
    float c_reg = 0.0f;
    float xg[4] = {0, 0, 0, 0};
    if (l < 8) {
        len = lengths[gb];
        #pragma unroll
        for (int g = 0; g < 4; ++g)
            xg[g] = g_xp[((size_t)g * H_ + j0 + ga) * B_ + gb];
    }
    __syncthreads();

    const uint32_t hs_b = (uint32_t)__cvta_generic_to_shared(h_s);
    int cur = 0;

    for (int step = 0; step < S_; ++step) {
        // warp-private cp.async: k-slice [kbase,+32) for 16 local batches
        // (r13 fill: 8 lanes per batch row = 128B contiguous)
        const float* hsrc = g_hbuf[cur];
        #pragma unroll
        for (int q = 0; q < 4; ++q) {
            int c  = q * 32 + l;
            int b2 = c >> 3;
            int ko = kbase + (c & 7) * 4;
            cp16(hs_b + (uint32_t)(b2 * 512 + (ko ^ (((b2 >> 2) & 3) << 2))) * 4u,
                 hsrc + (size_t)(bbase + b2) * H_ + ko);
        }
        asm volatile("cp.async.commit_group;");

        u64 acc[4][4];
        #pragma unroll
        for (int a = 0; a < 4; ++a)
            #pragma unroll
            for (int b = 0; b < 4; ++b) acc[a][b] = 0ull;

        asm volatile("cp.async.wait_group 0;");
        __syncwarp();

        const int hswz = v << 2;
        #pragma unroll
        for (int kq = 0; kq < 8; ++kq) {
            int k  = kbase + kq * 4;
            int kh = kbase + ((kq * 4) ^ hswz);
            ulonglong2 hv[4], wv[4];
            #pragma unroll
            for (int bi = 0; bi < 4; ++bi)
                hv[bi] = *(const ulonglong2*)&h_s[(4 * v + bi) * 512 + kh];
            #pragma unroll
            for (int ci = 0; ci < 4; ++ci)
                wv[ci] = *(const ulonglong2*)&W_s[(u + 8 * ci) * WP + k];
            #pragma unroll
            for (int ci = 0; ci < 4; ++ci)
                #pragma unroll
                for (int bi = 0; bi < 4; ++bi) {
                    acc[ci][bi] = ffma2(hv[bi].x, wv[ci].x, acc[ci][bi]);
                    acc[ci][bi] = ffma2(hv[bi].y, wv[ci].y, acc[ci][bi]);
                }
        }

        // prefetch next xp (overlaps reduction + gates + barrier)
        float xgn[4];
        if (l < 8 && step + 1 < S_) {
            #pragma unroll
            for (int g = 0; g < 4; ++g)
                xgn[g] = g_xp[((size_t)((step + 1) * 4 + g) * H_ + j0 + ga) * B_ + gb];
        }

        #pragma unroll
        for (int ci = 0; ci < 4; ++ci)
            #pragma unroll
            for (int bi = 0; bi < 4; ++bi) {
                float2 p = unpack2(acc[ci][bi]);
                part[(w * 32 + u + 8 * ci) * PSTR + 4 * v + bi] = p.x + p.y;
            }
        __syncthreads();

        // warp w reduces all 32 gate rows of batch w (lane = row; CF banks)
        float s = 0.0f;
        #pragma unroll
        for (int ww = 0; ww < NW; ++ww)
            s += part[(ww * 32 + l) * PSTR + w];

        // gates via in-warp gather: lane a<8 collects rows 4a..4a+3
        float h = 0.0f;
        {
            float gi = __shfl_sync(0xffffffffu, s, (l & 7) * 4 + 0);
            float gf = __shfl_sync(0xffffffffu, s, (l & 7) * 4 + 1);
            float gg = __shfl_sync(0xffffffffu, s, (l & 7) * 4 + 2);
            float go = __shfl_sync(0xffffffffu, s, (l & 7) * 4 + 3);
            if (l < 8) {
                float i_ = fsig(gi + xg[0]);
                float f_ = fsig(gf + xg[1]);
                float g_ = ftanh_(gg + xg[2]);
                float o_ = fsig(go + xg[3]);
                c_reg = f_ * c_reg + i_ * g_;
                h = o_ * ftanh_(c_reg);
                g_hbuf[cur ^ 1][gb * H_ + j0 + ga] = h;
            }
        }
        __syncthreads();               // hbuf stores ordered before release

        if (t == 0) red_add_rel(my_ctr, 1u);

        // off-critical-path work while arrivals accumulate
        if (l < 8) {
            out[((size_t)gb * S_ + step) * H_ + j0 + ga] = (step < len) ? h : 0.0f;
            if (step == len - 1) g_hidden[gb * H_ + j0 + ga] = h;
            #pragma unroll
            for (int g = 0; g < 4; ++g) xg[g] = xgn[g];
        }

        // group barrier wait: t0 acquire-poll on own group's counter
        if (t == 0) {
            const unsigned int tgt = (unsigned int)(step + 1) * 64u;
            while (ld_acq(my_ctr) < tgt) { }
        }
        __syncthreads();
        cur ^= 1;
    }
}

__global__ void finalize(const int* __restrict__ lengths, float* __restrict__ d_out,
                         int out_size)
{
    const int base = B_ * S_ * H_;
    int t = blockIdx.x * blockDim.x + threadIdx.x;
    if (out_size >= base + B_ && t < B_)
        d_out[base + t] = (float)lengths[t];
    if (out_size >= base + B_ + B_ * H_) {
        for (int i = t; i < B_ * H_; i += blockDim.x * gridDim.x)
            d_out[base + B_ + i] = g_hidden[i];
    }
}

extern "C" void kernel_launch(void* const* d_in, const int* in_sizes, int n_in,
                              void* d_out, int out_size)
{
    const float* x       = (const float*)d_in[0];
    const int*   lengths = (const int*)d_in[1];
    const float* Wih     = (const float*)d_in[2];
    const float* Whh     = (const float*)d_in[3];
    const float* bih     = (const float*)d_in[4];
    const float* bhh     = (const float*)d_in[5];
    float* out = (float*)d_out;

    cudaFuncSetAttribute(lstm_rec, cudaFuncAttributeMaxDynamicSharedMemorySize,
                         SMEM_REC);

    dummy_k<<<1, 32>>>();    // keeps ncu's sampled slot on lstm_rec
    init_k<<<32, 256>>>();
    dim3 g1(512, 16);
    gemm_xproj<<<g1, 256>>>(x, Wih, bih, bhh);
    lstm_rec<<<NBLK, 512, SMEM_REC>>>(Whh, lengths, out);
    finalize<<<64, 256>>>(lengths, out, out_size);
}

// round 17
// speedup vs baseline: 1.2421x; 1.0453x over previous
#include <cuda_runtime.h>
#include <cstdint>

#define B_ 32
#define S_ 2048
#define E_ 512
#define H_ 512
#define NBLK 128
#define NW 16
#define WP 516
#define PSTR 37
#define GSTRD 17
#define GSTR 132

typedef unsigned long long u64;

// x_proj layout: [s][gate][j][b]
__device__ float g_xp[(size_t)S_ * 4 * H_ * B_];
__device__ float g_hbuf[2][B_ * H_];
__device__ float g_hidden[B_ * H_];
__device__ unsigned int g_ctr[64];   // [0]: group 0, [32]: group 1

__device__ __forceinline__ u64 ffma2(u64 a, u64 b, u64 c) {
    u64 d;
    asm("fma.rn.f32x2 %0, %1, %2, %3;" : "=l"(d) : "l"(a), "l"(b), "l"(c));
    return d;
}
__device__ __forceinline__ u64 pack2(float x, float y) {
    u64 r;
    asm("mov.b64 %0, {%1, %2};" : "=l"(r) : "f"(x), "f"(y));
    return r;
}
__device__ __forceinline__ float2 unpack2(u64 v) {
    float2 r;
    asm("mov.b64 {%0, %1}, %2;" : "=f"(r.x), "=f"(r.y) : "l"(v));
    return r;
}
__device__ __forceinline__ void cp16(uint32_t dst, const void* src) {
    asm volatile("cp.async.ca.shared.global [%0], [%1], 16;" :: "r"(dst), "l"(src));
}
__device__ __forceinline__ void red_add_rel(unsigned int* p, unsigned int v) {
    asm volatile("red.release.gpu.global.add.u32 [%0], %1;" :: "l"(p), "r"(v) : "memory");
}
__device__ __forceinline__ unsigned int ld_acq(const unsigned int* p) {
    unsigned int v;
    asm volatile("ld.acquire.gpu.global.u32 %0, [%1];" : "=r"(v) : "l"(p) : "memory");
    return v;
}
__device__ __forceinline__ float fsig(float x) {
    return __fdividef(1.0f, 1.0f + __expf(-x));
}
__device__ __forceinline__ float ftanh_(float x) {
    return __fdividef(2.0f, 1.0f + __expf(-2.0f * x)) - 1.0f;
}

__global__ void dummy_k() {}

__global__ void init_k() {
    int t = blockIdx.x * blockDim.x + threadIdx.x;
    if (t < 64) g_ctr[t] = 0u;
    for (int i = t; i < B_ * H_; i += blockDim.x * gridDim.x)
        g_hbuf[0][i] = 0.0f;
}

// ------------- GEMM: x_proj = x @ W_ih^T + (b_ih+b_hh) (at FFMA2 floor) -------
__global__ void __launch_bounds__(256, 2) gemm_xproj(
    const float* __restrict__ x, const float* __restrict__ Wih,
    const float* __restrict__ bih, const float* __restrict__ bhh)
{
    __shared__ float As[2][16 * GSTR];
    __shared__ float Bs[2][16 * GSTR];

    const int t  = threadIdx.x;
    const int s0 = blockIdx.x;
    const int n0 = blockIdx.y * 128;
    const int tx = t & 15, ty = t >> 4;
    const int lr = t >> 2;
    const int lq = t & 3;

    const size_t rowA0 = (size_t)((lr & 31) * S_ + s0 * 4 + (lr >> 5)) * E_;
    const size_t rowA1 = (size_t)(((lr + 64) & 31) * S_ + s0 * 4 + ((lr + 64) >> 5)) * E_;
    const size_t rowB0 = (size_t)(n0 + lr) * E_;
    const size_t rowB1 = (size_t)(n0 + lr + 64) * E_;

    u64 acc[8][4];
    #pragma unroll
    for (int i = 0; i < 8; ++i)
        #pragma unroll
        for (int j = 0; j < 4; ++j) acc[i][j] = 0ull;

    float4 a0 = *(const float4*)&x[rowA0 + lq * 4];
    float4 a1 = *(const float4*)&x[rowA1 + lq * 4];
    float4 b0 = *(const float4*)&Wih[rowB0 + lq * 4];
    float4 b1 = *(const float4*)&Wih[rowB1 + lq * 4];
    {
        float va0[4] = {a0.x, a0.y, a0.z, a0.w};
        float va1[4] = {a1.x, a1.y, a1.z, a1.w};
        float vb0[4] = {b0.x, b0.y, b0.z, b0.w};
        float vb1[4] = {b1.x, b1.y, b1.z, b1.w};
        #pragma unroll
        for (int i = 0; i < 4; ++i) {
            As[0][(lq * 4 + i) * GSTR + lr]      = va0[i];
            As[0][(lq * 4 + i) * GSTR + lr + 64] = va1[i];
            Bs[0][(lq * 4 + i) * GSTR + lr]      = vb0[i];
            Bs[0][(lq * 4 + i) * GSTR + lr + 64] = vb1[i];
        }
    }
    __syncthreads();

    for (int st = 0; st < 32; ++st) {
        const int cb = st & 1;
        if (st < 31) {
            int k0 = (st + 1) * 16;
            a0 = *(const float4*)&x[rowA0 + k0 + lq * 4];
            a1 = *(const float4*)&x[rowA1 + k0 + lq * 4];
            b0 = *(const float4*)&Wih[rowB0 + k0 + lq * 4];
            b1 = *(const float4*)&Wih[rowB1 + k0 + lq * 4];
        }
        #pragma unroll
        for (int kk = 0; kk < 16; ++kk) {
            float4 av0 = *(const float4*)&As[cb][kk * GSTR + ty * 8];
            float4 av1 = *(const float4*)&As[cb][kk * GSTR + ty * 8 + 4];
            ulonglong2 bv0 = *(const ulonglong2*)&Bs[cb][kk * GSTR + 4 * tx];
            ulonglong2 bv1 = *(const ulonglong2*)&Bs[cb][kk * GSTR + 64 + 4 * tx];
            float av[8] = {av0.x, av0.y, av0.z, av0.w, av1.x, av1.y, av1.z, av1.w};
            u64 bb[4] = {bv0.x, bv0.y, bv1.x, bv1.y};
            #pragma unroll
            for (int i = 0; i < 8; ++i) {
                u64 ad = pack2(av[i], av[i]);
                #pragma unroll
                for (int j = 0; j < 4; ++j)
                    acc[i][j] = ffma2(ad, bb[j], acc[i][j]);
            }
        }
        if (st < 31) {
            const int nb = cb ^ 1;
            float va0[4] = {a0.x, a0.y, a0.z, a0.w};
            float va1[4] = {a1.x, a1.y, a1.z, a1.w};
            float vb0[4] = {b0.x, b0.y, b0.z, b0.w};
            float vb1[4] = {b1.x, b1.y, b1.z, b1.w};
            #pragma unroll
            for (int i = 0; i < 4; ++i) {
                As[nb][(lq * 4 + i) * GSTR + lr]      = va0[i];
                As[nb][(lq * 4 + i) * GSTR + lr + 64] = va1[i];
                Bs[nb][(lq * 4 + i) * GSTR + lr]      = vb0[i];
                Bs[nb][(lq * 4 + i) * GSTR + lr + 64] = vb1[i];
            }
        }
        __syncthreads();
    }

    float fa[8][8];
    #pragma unroll
    for (int i = 0; i < 8; ++i)
        #pragma unroll
        for (int j = 0; j < 4; ++j) {
            float2 v = unpack2(acc[i][j]);
            fa[i][2 * j] = v.x;
            fa[i][2 * j + 1] = v.y;
        }

    const int si  = ty >> 2;
    const int b0r = (ty & 3) * 8;
    const int s   = s0 * 4 + si;
    #pragma unroll
    for (int np = 0; np < 8; ++np) {
        int n = n0 + ((np < 4) ? (4 * tx + np) : (64 + 4 * tx + (np - 4)));
        float bias = bih[n] + bhh[n];
        int gt = n >> 9, jd = n & (H_ - 1);
        size_t base = ((size_t)(s * 4 + gt) * H_ + jd) * B_ + b0r;
        float4 v0 = {fa[0][np] + bias, fa[1][np] + bias, fa[2][np] + bias, fa[3][np] + bias};
        float4 v1 = {fa[4][np] + bias, fa[5][np] + bias, fa[6][np] + bias, fa[7][np] + bias};
        *(float4*)&g_xp[base]     = v0;
        *(float4*)&g_xp[base + 4] = v1;
    }
}

// ------------- persistent recurrence: 128 CTAs x 512 threads -------------
// r13 structure exactly; the pre-release barrier is narrowed to the 128
// gate threads (bar.sync 1,128) so t0's release doesn't wait on warps 4-15.
#define SM_FLOATS (32 * WP + 16 * 512 + NW * 32 * PSTR + 32 * GSTRD)
#define SMEM_REC  (SM_FLOATS * 4)

__global__ void __launch_bounds__(512, 1) lstm_rec(
    const float* __restrict__ Whh, const int* __restrict__ lengths,
    float* __restrict__ out)
{
    extern __shared__ float sm[];
    float* W_s  = sm;                          // 32 x WP(516)
    float* h_s  = sm + 32 * WP;                // 16 x 512, XOR-swizzled
    float* part = h_s + 16 * 512;              // NW x 32 x PSTR(37)
    float* gsum = part + NW * 32 * PSTR;       // 32 x GSTRD(17)

    const int t  = threadIdx.x;
    const int w  = t >> 5;
    const int l  = t & 31;
    const int u  = l >> 2;
    const int v  = l & 3;
    const int j0    = (blockIdx.x >> 1) * 8;
    const int bh    = blockIdx.x & 1;
    const int bbase = bh * 16;
    const int kbase = w * 32;
    unsigned int* my_ctr = &g_ctr[bh * 32];

    // W_s row r = 4*jl + g  <-  W_hh[g*H + j0+jl][:]
    for (int idx = t; idx < 32 * 512; idx += 512) {
        int r = idx >> 9, k = idx & 511;
        W_s[r * WP + k] = Whh[(size_t)((r & 3) * H_ + j0 + (r >> 2)) * H_ + k];
    }

    const int rr = t & 31;
    const int rb = t >> 5;
    const int gjl = t & 7;
    const int gbl = t >> 3;
    int len = 0;
    float c_reg = 0.0f;
    float xg[4] = {0, 0, 0, 0};
    if (t < 128) {
        len = lengths[bbase + gbl];
        #pragma unroll
        for (int g = 0; g < 4; ++g)
            xg[g] = g_xp[((size_t)g * H_ + j0 + gjl) * B_ + bbase + gbl];
    }
    __syncthreads();

    const uint32_t hs_b = (uint32_t)__cvta_generic_to_shared(h_s);
    int cur = 0;

    for (int step = 0; step < S_; ++step) {
        // warp-private cp.async: k-slice [kbase,+32) for 16 local batches
        const float* hsrc = g_hbuf[cur];
        #pragma unroll
        for (int q = 0; q < 4; ++q) {
            int c  = q * 32 + l;
            int b2 = c >> 3;
            int ko = kbase + (c & 7) * 4;
            cp16(hs_b + (uint32_t)(b2 * 512 + (ko ^ (((b2 >> 2) & 3) << 2))) * 4u,
                 hsrc + (size_t)(bbase + b2) * H_ + ko);
        }
        asm volatile("cp.async.commit_group;");

        u64 acc[4][4];
        #pragma unroll
        for (int a = 0; a < 4; ++a)
            #pragma unroll
            for (int b = 0; b < 4; ++b) acc[a][b] = 0ull;

        asm volatile("cp.async.wait_group 0;");
        __syncwarp();

        const int hswz = v << 2;
        #pragma unroll
        for (int kq = 0; kq < 8; ++kq) {
            int k  = kbase + kq * 4;
            int kh = kbase + ((kq * 4) ^ hswz);
            ulonglong2 hv[4], wv[4];
            #pragma unroll
            for (int bi = 0; bi < 4; ++bi)
                hv[bi] = *(const ulonglong2*)&h_s[(4 * v + bi) * 512 + kh];
            #pragma unroll
            for (int ci = 0; ci < 4; ++ci)
                wv[ci] = *(const ulonglong2*)&W_s[(u + 8 * ci) * WP + k];
            #pragma unroll
            for (int ci = 0; ci < 4; ++ci)
                #pragma unroll
                for (int bi = 0; bi < 4; ++bi) {
                    acc[ci][bi] = ffma2(hv[bi].x, wv[ci].x, acc[ci][bi]);
                    acc[ci][bi] = ffma2(hv[bi].y, wv[ci].y, acc[ci][bi]);
                }
        }

        // prefetch next xp (overlaps reduction + gates + barrier)
        float xgn[4];
        if (t < 128 && step + 1 < S_) {
            #pragma unroll
            for (int g = 0; g < 4; ++g)
                xgn[g] = g_xp[((size_t)((step + 1) * 4 + g) * H_ + j0 + gjl) * B_
                              + bbase + gbl];
        }

        #pragma unroll
        for (int ci = 0; ci < 4; ++ci)
            #pragma unroll
            for (int bi = 0; bi < 4; ++bi) {
                float2 p = unpack2(acc[ci][bi]);
                part[(w * 32 + u + 8 * ci) * PSTR + 4 * v + bi] = p.x + p.y;
            }
        __syncthreads();

        // reduction: 512 threads, one (gate row rr, local batch rb) each
        {
            float s = 0.0f;
            #pragma unroll
            for (int ww = 0; ww < NW; ++ww)
                s += part[(ww * 32 + rr) * PSTR + rb];
            gsum[rr * GSTRD + rb] = s;
        }
        __syncthreads();

        // gates (warps 0-3): only g_hbuf must precede the release
        float h = 0.0f;
        if (t < 128) {
            float gv[4];
            #pragma unroll
            for (int g = 0; g < 4; ++g)
                gv[g] = xg[g] + gsum[(4 * gjl + g) * GSTRD + gbl];
            float i_ = fsig(gv[0]);
            float f_ = fsig(gv[1]);
            float g_ = ftanh_(gv[2]);
            float o_ = fsig(gv[3]);
            c_reg = f_ * c_reg + i_ * g_;
            h = o_ * ftanh_(c_reg);
            g_hbuf[cur ^ 1][(bbase + gbl) * H_ + j0 + gjl] = h;
            // narrow barrier: only gate warps (0-3) must order before release
            asm volatile("bar.sync 1, 128;" ::: "memory");
        }

        if (t == 0) red_add_rel(my_ctr, 1u);

        // off-critical-path work while arrivals accumulate
        if (t < 128) {
            int b = bbase + gbl, j = j0 + gjl;
            out[((size_t)b * S_ + step) * H_ + j] = (step < len) ? h : 0.0f;
            if (step == len - 1) g_hidden[b * H_ + j] = h;
            #pragma unroll
            for (int g = 0; g < 4; ++g) xg[g] = xgn[g];
        }

        // group barrier wait: t0 acquire-poll on own group's counter
        if (t == 0) {
            const unsigned int tgt = (unsigned int)(step + 1) * 64u;
            while (ld_acq(my_ctr) < tgt) { }
        }
        __syncthreads();
        cur ^= 1;
    }
}

__global__ void finalize(const int* __restrict__ lengths, float* __restrict__ d_out,
                         int out_size)
{
    const int base = B_ * S_ * H_;
    int t = blockIdx.x * blockDim.x + threadIdx.x;
    if (out_size >= base + B_ && t < B_)
        d_out[base + t] = (float)lengths[t];
    if (out_size >= base + B_ + B_ * H_) {
        for (int i = t; i < B_ * H_; i += blockDim.x * gridDim.x)
            d_out[base + B_ + i] = g_hidden[i];
    }
}

extern "C" void kernel_launch(void* const* d_in, const int* in_sizes, int n_in,
                              void* d_out, int out_size)
{
    const float* x       = (const float*)d_in[0];
    const int*   lengths = (const int*)d_in[1];
    const float* Wih     = (const float*)d_in[2];
    const float* Whh     = (const float*)d_in[3];
    const float* bih     = (const float*)d_in[4];
    const float* bhh     = (const float*)d_in[5];
    float* out = (float*)d_out;

    cudaFuncSetAttribute(lstm_rec, cudaFuncAttributeMaxDynamicSharedMemorySize,
                         SMEM_REC);

    dummy_k<<<1, 32>>>();    // keeps ncu's sampled slot on lstm_rec
    init_k<<<32, 256>>>();
    dim3 g1(512, 16);
    gemm_xproj<<<g1, 256>>>(x, Wih, bih, bhh);
    lstm_rec<<<NBLK, 512, SMEM_REC>>>(Whh, lengths, out);
    finalize<<<64, 256>>>(lengths, out, out_size);
}